// round 7
// baseline (speedup 1.0000x reference)
#include <cuda_runtime.h>
#include <cuda_bf16.h>
#include <math.h>
#include <stdint.h>

#define NN   100000
#define OC   128
#define MAXE 1600000

// ---------------------------------------------------------------------------
// Device scratch
// ---------------------------------------------------------------------------
__device__ __align__(16) float g_A [(size_t)NN * OC];
__device__ __align__(16) float g_B [(size_t)NN * OC];
__device__ __align__(16) float g_x2[(size_t)NN * OC];
__device__ __align__(16) float g_x4[(size_t)NN * OC];
__device__ __align__(16) float g_x6[(size_t)NN * OC];

__device__ int g_deg[NN];
__device__ int g_off[NN + 1];
__device__ int g_cur[NN];
__device__ int g_ssrc[MAXE];
__device__ int g_sdst[MAXE];
// Pre-packed tf32 B operand per layer: [pair p(8)][kstep(16)][lane(32)] uint4
__device__ __align__(16) uint4 g_wbp[3][4096];
__device__ int g_idx64;

// ---------------------------------------------------------------------------
// tf32 / async-copy helpers
// ---------------------------------------------------------------------------
__device__ __forceinline__ uint32_t f2tf32(float f) {
    uint32_t r;
    asm("cvt.rna.tf32.f32 %0, %1;" : "=r"(r) : "f"(f));
    return r;
}

__device__ __forceinline__ void mma_tf32(float* d, const uint32_t* a,
                                         uint32_t b0, uint32_t b1) {
    asm volatile(
        "mma.sync.aligned.m16n8k8.row.col.f32.tf32.tf32.f32 "
        "{%0,%1,%2,%3}, {%4,%5,%6,%7}, {%8,%9}, {%0,%1,%2,%3};"
        : "+f"(d[0]), "+f"(d[1]), "+f"(d[2]), "+f"(d[3])
        : "r"(a[0]), "r"(a[1]), "r"(a[2]), "r"(a[3]), "r"(b0), "r"(b1));
}

__device__ __forceinline__ uint32_t smem_u32(const void* p) {
    uint32_t a;
    asm("{ .reg .u64 t; cvta.to.shared.u64 t, %1; cvt.u32.u64 %0, t; }"
        : "=r"(a) : "l"(p));
    return a;
}
#define CP_ASYNC16(dst_u32, src_ptr) \
    asm volatile("cp.async.ca.shared.global [%0], [%1], 16;" \
                 :: "r"(dst_u32), "l"(src_ptr))
#define CP_COMMIT()  asm volatile("cp.async.commit_group;" ::: "memory")
#define CP_WAIT0()   asm volatile("cp.async.wait_group 0;" ::: "memory")

// ---------------------------------------------------------------------------
// Index-width detection (int32 vs int64 edge_index)
// ---------------------------------------------------------------------------
__global__ void detect_idx_kernel(const int* __restrict__ ei)
{
    __shared__ int any;
    if (threadIdx.x == 0) any = 0;
    __syncthreads();
    for (int i = threadIdx.x; i < 2048; i += blockDim.x)
        if (ei[2 * i + 1] != 0) any = 1;
    __syncthreads();
    if (threadIdx.x == 0) g_idx64 = (any == 0) ? 1 : 0;
}

// ---------------------------------------------------------------------------
// Counting sort by dst
// ---------------------------------------------------------------------------
__global__ void hist_kernel(const void* __restrict__ ei, long long E, int* __restrict__ deg)
{
    const int idx64 = g_idx64;
    long long i = (long long)blockIdx.x * blockDim.x + threadIdx.x;
    const long long stride = (long long)gridDim.x * blockDim.x;
    for (; i < E; i += stride) {
        int d = idx64 ? (int)((const long long*)ei)[E + i] : ((const int*)ei)[E + i];
        atomicAdd(&deg[d], 1);
    }
}

__global__ void scan_kernel(const int* __restrict__ deg, int* __restrict__ off, int n)
{
    __shared__ int sc[1024];
    __shared__ int carry;
    const int tid = threadIdx.x;
    if (tid == 0) carry = 0;
    __syncthreads();
    for (int base = 0; base < n; base += 1024) {
        int i = base + tid;
        int v = (i < n) ? deg[i] : 0;
        sc[tid] = v;
        __syncthreads();
        int run = v;
        for (int d = 1; d < 1024; d <<= 1) {
            int add = (tid >= d) ? sc[tid - d] : 0;
            __syncthreads();
            run += add;
            sc[tid] = run;
            __syncthreads();
        }
        int c = carry;
        if (i < n) off[i] = c + run - v;
        __syncthreads();
        if (tid == 0) carry = c + sc[1023];
        __syncthreads();
    }
    if (tid == 0) off[n] = carry;
}

__global__ void scatter_kernel(const void* __restrict__ ei, long long E,
                               const int* __restrict__ off, int* __restrict__ cur,
                               int* __restrict__ ssrc, int* __restrict__ sdst)
{
    const int idx64 = g_idx64;
    long long i = (long long)blockIdx.x * blockDim.x + threadIdx.x;
    const long long stride = (long long)gridDim.x * blockDim.x;
    for (; i < E; i += stride) {
        int s, d;
        if (idx64) { s = (int)((const long long*)ei)[i]; d = (int)((const long long*)ei)[E + i]; }
        else       { s = ((const int*)ei)[i];            d = ((const int*)ei)[E + i]; }
        int p = off[d] + atomicAdd(&cur[d], 1);
        ssrc[p] = s;
        sdst[p] = d;
    }
}

// ---------------------------------------------------------------------------
// Pack wb [K=128 in][N=128 out] into per-lane tf32 B fragments (m16n8k8).
// ---------------------------------------------------------------------------
__global__ void prep_w_kernel(const float* __restrict__ wb, uint4* __restrict__ outp)
{
    int idx = blockIdx.x * blockDim.x + threadIdx.x;
    if (idx >= 4096) return;
    int lane = idx & 31;
    int kk   = (idx >> 5) & 15;
    int p    = idx >> 9;
    int k0 = kk * 8 + (lane & 3);
    int n0 = p * 16 + (lane >> 2);
    uint4 v;
    v.x = f2tf32(wb[k0 * 128 + n0]);
    v.y = f2tf32(wb[(k0 + 4) * 128 + n0]);
    v.z = f2tf32(wb[k0 * 128 + n0 + 8]);
    v.w = f2tf32(wb[(k0 + 4) * 128 + n0 + 8]);
    outp[idx] = v;
}

// ---------------------------------------------------------------------------
// Node transform: A = x @ (Wtop - Wbot) + ba ;  B = x @ Wbot ; outz = 0
// ---------------------------------------------------------------------------
template<int C, int NPB>
__global__ __launch_bounds__(128)
void node_kernel(const float* __restrict__ x,
                 const float* __restrict__ wa,
                 const float* __restrict__ ba,
                 float* __restrict__ A,
                 float* __restrict__ B,
                 float* __restrict__ outz,
                 int n_nodes)
{
    __shared__ float xs[NPB * C];
    const int n0  = blockIdx.x * NPB;
    const int tid = threadIdx.x;

    for (int i = tid; i < NPB * C; i += 128) {
        int nn = i / C, c = i % C;
        int n = n0 + nn;
        xs[i] = (n < n_nodes) ? x[(size_t)n * C + c] : 0.f;
    }
    __syncthreads();

    float a[NPB], b[NPB];
#pragma unroll
    for (int t = 0; t < NPB; t++) { a[t] = 0.f; b[t] = 0.f; }

    const int o = tid;
#pragma unroll 4
    for (int c = 0; c < C; c++) {
        float wtop = wa[(size_t)c       * OC + o];
        float wbot = wa[(size_t)(C + c) * OC + o];
        float wd   = wtop - wbot;
#pragma unroll
        for (int t = 0; t < NPB; t++) {
            float xv = xs[t * C + c];
            a[t] += xv * wd;
            b[t] += xv * wbot;
        }
    }
    float bao = ba[o];
#pragma unroll
    for (int t = 0; t < NPB; t++) {
        int n = n0 + t;
        if (n < n_nodes) {
            size_t idx = (size_t)n * OC + o;
            A[idx]    = a[t] + bao;
            B[idx]    = b[t];
            outz[idx] = 0.f;
        }
    }
}

// ---------------------------------------------------------------------------
// Edge kernel (mma.sync tf32, sorted edges, cp.async pipelined B gather).
// Per 128-edge tile:
//   Bs[e][:]  <- cp.async  B[src[e]]   (issued one tile AHEAD, hidden under MMA)
//   H[e][k] = tf32(relu(A[dst] + Bs))  (A loads mostly L1: dst sorted)
//   D = H @ Wb  (m16n8k8 tf32, warp tile 32x64)
//   segmented max over contiguous dst runs + bias; plain store interior,
//   atomicMax(int-bits) on tile-boundary segments.
// ---------------------------------------------------------------------------
#define HP 132  // padded row stride (floats) for H / msg / Bs

#define SM_H     0                          // 128*132*4 = 67584
#define SM_WB    67584                      // 65536
#define SM_BS    (SM_WB + 65536)            // 133120: 128*132*4 = 67584
#define SM_SDST  (SM_BS + 67584)            // 200704: int[2][128]
#define SM_SSRC  (SM_SDST + 1024)           // int[2][128]
#define SM_SEGS  (SM_SSRC + 1024)           // int[136]
#define SM_SEGN  (SM_SEGS + 544)            // int[128]
#define SM_BB    (SM_SEGN + 512)            // float[128]
#define SM_WC    (SM_BB + 512)              // int[8]
#define SM_NSEG  (SM_WC + 32)               // int[4]
#define SM_TOTAL (SM_NSEG + 16)             // 204816

__global__ __launch_bounds__(256, 1)
void edge_mma_kernel(const float4* __restrict__ nodeA,
                     const float*  __restrict__ nodeBf,
                     const int* __restrict__ ssrc_g,
                     const int* __restrict__ sdst_g,
                     const uint4* __restrict__ wbp,
                     const float* __restrict__ bb,
                     float* __restrict__ out,
                     int E)
{
    extern __shared__ __align__(16) char smem[];
    const int tid  = threadIdx.x;
    const int wid  = tid >> 5;
    const int lane = tid & 31;
    const unsigned FULL = 0xffffffffu;

    uint32_t* Hs   = (uint32_t*)(smem + SM_H);
    float*    msg  = (float*)(smem + SM_H);      // same region, after MMA
    uint4*    wbs  = (uint4*)(smem + SM_WB);
    float*    Bs   = (float*)(smem + SM_BS);
    int*      sdstb= (int*)(smem + SM_SDST);     // [2][128]
    int*      ssrcb= (int*)(smem + SM_SSRC);     // [2][128]
    int*      segs = (int*)(smem + SM_SEGS);
    int*      segn = (int*)(smem + SM_SEGN);
    float*    bbs  = (float*)(smem + SM_BB);
    int*      swc  = (int*)(smem + SM_WC);
    int*      snseg= (int*)(smem + SM_NSEG);

    // persistent: packed weights + bias
    for (int i = tid; i < 4096; i += 256) wbs[i] = wbp[i];
    if (tid < 128) bbs[tid] = bb[tid];

    const int ntiles = (E + 127) >> 7;
    const int wM = wid & 3;      // edge-stripe  [wM*32, +32)
    const int wN = wid >> 2;     // out-half     [wN*64, +64)

    const int eb   = tid & 127;  // edge within tile this thread stages/computes
    const int half = tid >> 7;   // which 64-float half of the row
    const uint32_t bs_dst = smem_u32(Bs + eb * HP + half * 64);

    // ---- prologue: stage tile0's indices + B rows ----
    int cur = 0;
    {
        const int t0 = blockIdx.x;
        if (t0 < ntiles) {
            const int e0  = t0 << 7;
            const int cnt = min(128, E - e0);
            int sg = (eb < cnt) ? ssrc_g[e0 + eb] : 0;
            if (tid < 128) {
                sdstb[tid] = (tid < cnt) ? sdst_g[e0 + tid] : -1;
                ssrcb[tid] = sg;
            }
            const float* srcp = nodeBf + (size_t)sg * 128 + half * 64;
#pragma unroll
            for (int j = 0; j < 16; j++)
                CP_ASYNC16(bs_dst + j * 16, srcp + j * 4);
        }
        CP_COMMIT();
    }

    for (int t = blockIdx.x; t < ntiles; t += gridDim.x) {
        const int e0  = t << 7;
        const int cnt = min(128, E - e0);
        int* sdst = sdstb + cur * 128;

        CP_WAIT0();
        __syncthreads();   // Bs + index buffers ready, visible to all

        // ---- segment heads (warps 0..3) ----
        int head = 0; unsigned bm = 0;
        if (tid < 128) {
            head = (tid < cnt) && (tid == 0 || sdst[tid] != sdst[tid - 1]);
            bm = __ballot_sync(FULL, head);
            if (lane == 0) swc[wid] = __popc(bm);
        }
        __syncthreads();
        if (tid == 0) {
            int s = 0;
            for (int w = 0; w < 4; w++) { swc[4 + w] = s; s += swc[w]; }
            snseg[0] = s;
            segs[s]  = cnt;
        }
        __syncthreads();
        if (head) {
            int sid = swc[4 + wid] + __popc(bm & ((1u << lane) - 1u));
            segs[sid] = tid;
            segn[sid] = sdst[tid];
        }

        // ---- H[e][k] = tf32(relu(A[dst] + Bs)) ----
        {
            uint32_t* hr = Hs + eb * HP + half * 64;
            const float* br = Bs + eb * HP + half * 64;
            if (eb < cnt) {
                const size_t dr = (size_t)sdst[eb] * 32 + half * 16;
#pragma unroll
                for (int j = 0; j < 16; j++) {
                    float4 av = nodeA[dr + j];
                    float4 bv = *(const float4*)(br + j * 4);
                    uint4 hv;
                    hv.x = f2tf32(fmaxf(av.x + bv.x, 0.f));
                    hv.y = f2tf32(fmaxf(av.y + bv.y, 0.f));
                    hv.z = f2tf32(fmaxf(av.z + bv.z, 0.f));
                    hv.w = f2tf32(fmaxf(av.w + bv.w, 0.f));
                    *(uint4*)(hr + j * 4) = hv;
                }
            } else {
#pragma unroll
                for (int j = 0; j < 16; j++)
                    *(uint4*)(hr + j * 4) = make_uint4(0u, 0u, 0u, 0u);
            }
        }
        __syncthreads();   // H complete; Bs now dead

        // ---- prefetch tile t+gridDim.x: indices + cp.async B rows ----
        {
            const int tn = t + gridDim.x;
            if (tn < ntiles) {
                const int e0n  = tn << 7;
                const int cntn = min(128, E - e0n);
                int sg = (eb < cntn) ? ssrc_g[e0n + eb] : 0;
                if (tid < 128) {
                    sdstb[(cur ^ 1) * 128 + tid] = (tid < cntn) ? sdst_g[e0n + tid] : -1;
                    ssrcb[(cur ^ 1) * 128 + tid] = sg;
                }
                const float* srcp = nodeBf + (size_t)sg * 128 + half * 64;
#pragma unroll
                for (int j = 0; j < 16; j++)
                    CP_ASYNC16(bs_dst + j * 16, srcp + j * 4);
            }
            CP_COMMIT();
        }

        // ---- MMA: warp tile 32 edges x 64 outs ----
        float acc[2][8][4];
#pragma unroll
        for (int mt = 0; mt < 2; mt++)
#pragma unroll
            for (int nt = 0; nt < 8; nt++)
#pragma unroll
                for (int r = 0; r < 4; r++) acc[mt][nt][r] = 0.f;

        const int g = lane >> 2, th = lane & 3;
#pragma unroll 4
        for (int kk = 0; kk < 16; kk++) {
            uint32_t a[2][4];
#pragma unroll
            for (int mt = 0; mt < 2; mt++) {
                const uint32_t* base = Hs + (wM * 32 + mt * 16 + g) * HP + kk * 8 + th;
                a[mt][0] = base[0];
                a[mt][1] = base[8 * HP];
                a[mt][2] = base[4];
                a[mt][3] = base[8 * HP + 4];
            }
#pragma unroll
            for (int p = 0; p < 4; p++) {
                uint4 bp = wbs[((wN * 4 + p) * 16 + kk) * 32 + lane];
#pragma unroll
                for (int mt = 0; mt < 2; mt++) {
                    mma_tf32(acc[mt][2 * p],     a[mt], bp.x, bp.y);
                    mma_tf32(acc[mt][2 * p + 1], a[mt], bp.z, bp.w);
                }
            }
        }
        __syncthreads();   // all warps done reading H

        // ---- store D -> msg[e][c] ----
#pragma unroll
        for (int mt = 0; mt < 2; mt++) {
            const int row = wM * 32 + mt * 16 + g;
#pragma unroll
            for (int nt = 0; nt < 8; nt++) {
                const int col = wN * 64 + nt * 8 + 2 * th;
                *(float2*)(msg + row * HP + col) =
                    make_float2(acc[mt][nt][0], acc[mt][nt][1]);
                *(float2*)(msg + (row + 8) * HP + col) =
                    make_float2(acc[mt][nt][2], acc[mt][nt][3]);
            }
        }
        __syncthreads();

        // ---- segmented max + writeback ----
        {
            const int nseg = snseg[0];
            for (int i = tid; i < nseg * 128; i += 256) {
                const int c = i & 127;
                const int s = i >> 7;
                const int st = segs[s], en = segs[s + 1];
                float m = -3.4e38f;
                for (int e = st; e < en; e++)
                    m = fmaxf(m, msg[e * HP + c]);
                m += bbs[c];
                float* o = out + (size_t)segn[s] * OC + c;
                if (st == 0 || en == cnt) {
                    atomicMax((int*)o, __float_as_int(m));  // 0-init => relu free
                } else {
                    *o = fmaxf(m, 0.f);                     // sole writer
                }
            }
        }
        __syncthreads();
        cur ^= 1;
    }
}

// ---------------------------------------------------------------------------
// Final: concat(x2,x4,x6) [384] -> maxpool(24) -> 16 -> @ fw + fb
// ---------------------------------------------------------------------------
__global__ __launch_bounds__(256)
void final_kernel(const float* __restrict__ x2,
                  const float* __restrict__ x4,
                  const float* __restrict__ x6,
                  const float* __restrict__ fw,
                  const float* __restrict__ fb,
                  float* __restrict__ out,
                  int n_nodes)
{
    const unsigned FULL = 0xffffffffu;
    const int lane = threadIdx.x & 31;
    const int warp = blockIdx.x * (blockDim.x >> 5) + (threadIdx.x >> 5);
    const int nw   = gridDim.x * (blockDim.x >> 5);

    for (int n = warp; n < n_nodes; n += nw) {
        float m = -3.4e38f;
        int idx0 = lane * 12;
#pragma unroll
        for (int i = 0; i < 12; i++) {
            int idx = idx0 + i;
            float v;
            if (idx < 128)       v = x2[(size_t)n * OC + idx];
            else if (idx < 256)  v = x4[(size_t)n * OC + idx - 128];
            else                 v = x6[(size_t)n * OC + idx - 256];
            m = fmaxf(m, v);
        }
        float mm = fmaxf(m, __shfl_xor_sync(FULL, m, 1));
        float part = ((lane & 1) == 0) ? mm * fw[lane >> 1] : 0.f;
#pragma unroll
        for (int off = 16; off >= 1; off >>= 1)
            part += __shfl_xor_sync(FULL, part, off);
        if (lane == 0) out[n] = part + fb[0];
    }
}

// ---------------------------------------------------------------------------
extern "C" void kernel_launch(void* const* d_in, const int* in_sizes, int n_in,
                              void* d_out, int out_size)
{
    const float* x   = (const float*)d_in[0];
    const void*  ei  = d_in[1];
    const float* w1a = (const float*)d_in[2];  const float* b1a = (const float*)d_in[3];
    const float* w1b = (const float*)d_in[4];  const float* b1b = (const float*)d_in[5];
    const float* w2a = (const float*)d_in[6];  const float* b2a = (const float*)d_in[7];
    const float* w2b = (const float*)d_in[8];  const float* b2b = (const float*)d_in[9];
    const float* w3a = (const float*)d_in[10]; const float* b3a = (const float*)d_in[11];
    const float* w3b = (const float*)d_in[12]; const float* b3b = (const float*)d_in[13];
    const float* fw  = (const float*)d_in[14]; const float* fb  = (const float*)d_in[15];
    float* out = (float*)d_out;

    const int       N = in_sizes[0] / 24;
    const long long E = in_sizes[1] / 2;

    float *A, *B, *X2, *X4, *X6;
    int *deg, *off, *cur, *ssrc, *sdst;
    uint4 *wbp;
    cudaGetSymbolAddress((void**)&A,    g_A);
    cudaGetSymbolAddress((void**)&B,    g_B);
    cudaGetSymbolAddress((void**)&X2,   g_x2);
    cudaGetSymbolAddress((void**)&X4,   g_x4);
    cudaGetSymbolAddress((void**)&X6,   g_x6);
    cudaGetSymbolAddress((void**)&deg,  g_deg);
    cudaGetSymbolAddress((void**)&off,  g_off);
    cudaGetSymbolAddress((void**)&cur,  g_cur);
    cudaGetSymbolAddress((void**)&ssrc, g_ssrc);
    cudaGetSymbolAddress((void**)&sdst, g_sdst);
    cudaGetSymbolAddress((void**)&wbp,  g_wbp);

    cudaFuncSetAttribute(edge_mma_kernel,
                         cudaFuncAttributeMaxDynamicSharedMemorySize, SM_TOTAL);

    // ---- edge-index width + counting sort by dst ----
    detect_idx_kernel<<<1, 256>>>((const int*)ei);
    cudaMemsetAsync(deg, 0, (size_t)N * sizeof(int));
    cudaMemsetAsync(cur, 0, (size_t)N * sizeof(int));
    hist_kernel<<<512, 256>>>(ei, E, deg);
    scan_kernel<<<1, 1024>>>(deg, off, N);
    scatter_kernel<<<512, 256>>>(ei, E, off, cur, ssrc, sdst);

    // ---- weight prep (tf32 packed B fragments) ----
    prep_w_kernel<<<16, 256>>>(w1b, wbp);
    prep_w_kernel<<<16, 256>>>(w2b, wbp + 4096);
    prep_w_kernel<<<16, 256>>>(w3b, wbp + 8192);

    const int NPB = 8;
    const int node_grid = (N + NPB - 1) / NPB;
    const int edge_grid = 148;

    // Layer 1 (C = 24)
    node_kernel<24, 8><<<node_grid, 128>>>(x, w1a, b1a, A, B, X2, N);
    edge_mma_kernel<<<edge_grid, 256, SM_TOTAL>>>((const float4*)A, B,
        ssrc, sdst, wbp, b1b, X2, (int)E);
    // Layer 2 (C = 128)
    node_kernel<128, 8><<<node_grid, 128>>>(X2, w2a, b2a, A, B, X4, N);
    edge_mma_kernel<<<edge_grid, 256, SM_TOTAL>>>((const float4*)A, B,
        ssrc, sdst, wbp + 4096, b2b, X4, (int)E);
    // Layer 3 (C = 128)
    node_kernel<128, 8><<<node_grid, 128>>>(X4, w3a, b3a, A, B, X6, N);
    edge_mma_kernel<<<edge_grid, 256, SM_TOTAL>>>((const float4*)A, B,
        ssrc, sdst, wbp + 8192, b3b, X6, (int)E);

    // Pool + final linear
    final_kernel<<<(N + 7) / 8, 256>>>(X2, X4, X6, fw, fb, out, N);
}

// round 8
// speedup vs baseline: 1.2749x; 1.2749x over previous
#include <cuda_runtime.h>
#include <cuda_bf16.h>
#include <math.h>
#include <stdint.h>

#define NN   100000
#define OC   128
#define MAXE 1600000

// ---------------------------------------------------------------------------
// Device scratch
// ---------------------------------------------------------------------------
__device__ __align__(16) float g_A [(size_t)NN * OC];
__device__ __align__(16) float g_B [(size_t)NN * OC];
__device__ __align__(16) float g_x2[(size_t)NN * OC];
__device__ __align__(16) float g_x4[(size_t)NN * OC];
__device__ __align__(16) float g_x6[(size_t)NN * OC];

__device__ int g_deg[NN];
__device__ int g_off[NN + 1];
__device__ int g_cur[NN];
__device__ int g_ssrc[MAXE];
__device__ int g_sdst[MAXE];
// Pre-packed tf32 B operand per layer: [pair p(8)][kstep(16)][lane(32)] uint4
__device__ __align__(16) uint4 g_wbp[3][4096];
__device__ int g_idx64;

// ---------------------------------------------------------------------------
// tf32 helpers
// ---------------------------------------------------------------------------
__device__ __forceinline__ uint32_t f2tf32(float f) {
    uint32_t r;
    asm("cvt.rna.tf32.f32 %0, %1;" : "=r"(r) : "f"(f));
    return r;
}

__device__ __forceinline__ void mma_tf32(float* d, const uint32_t* a,
                                         uint32_t b0, uint32_t b1) {
    asm volatile(
        "mma.sync.aligned.m16n8k8.row.col.f32.tf32.tf32.f32 "
        "{%0,%1,%2,%3}, {%4,%5,%6,%7}, {%8,%9}, {%0,%1,%2,%3};"
        : "+f"(d[0]), "+f"(d[1]), "+f"(d[2]), "+f"(d[3])
        : "r"(a[0]), "r"(a[1]), "r"(a[2]), "r"(a[3]), "r"(b0), "r"(b1));
}

// ---------------------------------------------------------------------------
// Index-width detection (int32 vs int64 edge_index)
// ---------------------------------------------------------------------------
__global__ void detect_idx_kernel(const int* __restrict__ ei)
{
    __shared__ int any;
    if (threadIdx.x == 0) any = 0;
    __syncthreads();
    for (int i = threadIdx.x; i < 2048; i += blockDim.x)
        if (ei[2 * i + 1] != 0) any = 1;
    __syncthreads();
    if (threadIdx.x == 0) g_idx64 = (any == 0) ? 1 : 0;
}

// ---------------------------------------------------------------------------
// Counting sort by dst
// ---------------------------------------------------------------------------
__global__ void hist_kernel(const void* __restrict__ ei, long long E, int* __restrict__ deg)
{
    const int idx64 = g_idx64;
    long long i = (long long)blockIdx.x * blockDim.x + threadIdx.x;
    const long long stride = (long long)gridDim.x * blockDim.x;
    for (; i < E; i += stride) {
        int d = idx64 ? (int)((const long long*)ei)[E + i] : ((const int*)ei)[E + i];
        atomicAdd(&deg[d], 1);
    }
}

__global__ void scan_kernel(const int* __restrict__ deg, int* __restrict__ off, int n)
{
    __shared__ int sc[1024];
    __shared__ int carry;
    const int tid = threadIdx.x;
    if (tid == 0) carry = 0;
    __syncthreads();
    for (int base = 0; base < n; base += 1024) {
        int i = base + tid;
        int v = (i < n) ? deg[i] : 0;
        sc[tid] = v;
        __syncthreads();
        int run = v;
        for (int d = 1; d < 1024; d <<= 1) {
            int add = (tid >= d) ? sc[tid - d] : 0;
            __syncthreads();
            run += add;
            sc[tid] = run;
            __syncthreads();
        }
        int c = carry;
        if (i < n) off[i] = c + run - v;
        __syncthreads();
        if (tid == 0) carry = c + sc[1023];
        __syncthreads();
    }
    if (tid == 0) off[n] = carry;
}

__global__ void scatter_kernel(const void* __restrict__ ei, long long E,
                               const int* __restrict__ off, int* __restrict__ cur,
                               int* __restrict__ ssrc, int* __restrict__ sdst)
{
    const int idx64 = g_idx64;
    long long i = (long long)blockIdx.x * blockDim.x + threadIdx.x;
    const long long stride = (long long)gridDim.x * blockDim.x;
    for (; i < E; i += stride) {
        int s, d;
        if (idx64) { s = (int)((const long long*)ei)[i]; d = (int)((const long long*)ei)[E + i]; }
        else       { s = ((const int*)ei)[i];            d = ((const int*)ei)[E + i]; }
        int p = off[d] + atomicAdd(&cur[d], 1);
        ssrc[p] = s;
        sdst[p] = d;
    }
}

// ---------------------------------------------------------------------------
// Pack wb [K=128 in][N=128 out] into per-lane tf32 B fragments (m16n8k8).
// ---------------------------------------------------------------------------
__global__ void prep_w_kernel(const float* __restrict__ wb, uint4* __restrict__ outp)
{
    int idx = blockIdx.x * blockDim.x + threadIdx.x;
    if (idx >= 4096) return;
    int lane = idx & 31;
    int kk   = (idx >> 5) & 15;
    int p    = idx >> 9;
    int k0 = kk * 8 + (lane & 3);
    int n0 = p * 16 + (lane >> 2);
    uint4 v;
    v.x = f2tf32(wb[k0 * 128 + n0]);
    v.y = f2tf32(wb[(k0 + 4) * 128 + n0]);
    v.z = f2tf32(wb[k0 * 128 + n0 + 8]);
    v.w = f2tf32(wb[(k0 + 4) * 128 + n0 + 8]);
    outp[idx] = v;
}

// ---------------------------------------------------------------------------
// Node transform: A = x @ (Wtop - Wbot) + ba ;  B = x @ Wbot ; outz = 0
// ---------------------------------------------------------------------------
template<int C, int NPB>
__global__ __launch_bounds__(128)
void node_kernel(const float* __restrict__ x,
                 const float* __restrict__ wa,
                 const float* __restrict__ ba,
                 float* __restrict__ A,
                 float* __restrict__ B,
                 float* __restrict__ outz,
                 int n_nodes)
{
    __shared__ float xs[NPB * C];
    const int n0  = blockIdx.x * NPB;
    const int tid = threadIdx.x;

    for (int i = tid; i < NPB * C; i += 128) {
        int nn = i / C, c = i % C;
        int n = n0 + nn;
        xs[i] = (n < n_nodes) ? x[(size_t)n * C + c] : 0.f;
    }
    __syncthreads();

    float a[NPB], b[NPB];
#pragma unroll
    for (int t = 0; t < NPB; t++) { a[t] = 0.f; b[t] = 0.f; }

    const int o = tid;
#pragma unroll 4
    for (int c = 0; c < C; c++) {
        float wtop = wa[(size_t)c       * OC + o];
        float wbot = wa[(size_t)(C + c) * OC + o];
        float wd   = wtop - wbot;
#pragma unroll
        for (int t = 0; t < NPB; t++) {
            float xv = xs[t * C + c];
            a[t] += xv * wd;
            b[t] += xv * wbot;
        }
    }
    float bao = ba[o];
#pragma unroll
    for (int t = 0; t < NPB; t++) {
        int n = n0 + t;
        if (n < n_nodes) {
            size_t idx = (size_t)n * OC + o;
            A[idx]    = a[t] + bao;
            B[idx]    = b[t];
            outz[idx] = 0.f;
        }
    }
}

// ---------------------------------------------------------------------------
// Edge kernel (mma.sync tf32, sorted edges).
// 2 CTAs/SM: one CTA's gather/epilogue overlaps the other's HMMA phase.
// Weight fragments read from GLOBAL (L1/L2-hot: same 64KB every tile).
// Per 128-edge tile:
//   H[e][k] = tf32(relu(A[dst]+B[src])) -> smem (padded rows)
//   D[128 e][128 out] = H @ Wb via m16n8k8 tf32 mma, warp tile 32x64
//   segmented max over contiguous dst runs + bias; plain store interior,
//   atomicMax(int-bits) on tile-boundary segments.
// ---------------------------------------------------------------------------
#define HP 132  // padded row stride (floats) for H / msg

#define SM_H     0                          // 128*132*4 = 67584
#define SM_SDST  67584                      // int[128]
#define SM_SSRC  (SM_SDST + 512)            // int[128]
#define SM_SEGS  (SM_SSRC + 512)            // int[136]
#define SM_SEGN  (SM_SEGS + 544)            // int[128]
#define SM_BB    (SM_SEGN + 512)            // float[128]
#define SM_WC    (SM_BB + 512)              // int[8]
#define SM_NSEG  (SM_WC + 32)               // int[4]
#define SM_TOTAL (SM_NSEG + 16)             // 70240

__global__ __launch_bounds__(256, 2)
void edge_mma_kernel(const float4* __restrict__ nodeA,
                     const float4* __restrict__ nodeB,
                     const int* __restrict__ ssrc_g,
                     const int* __restrict__ sdst_g,
                     const uint4* __restrict__ wbp,
                     const float* __restrict__ bb,
                     float* __restrict__ out,
                     int E)
{
    extern __shared__ __align__(16) char smem[];
    const int tid  = threadIdx.x;
    const int wid  = tid >> 5;
    const int lane = tid & 31;
    const unsigned FULL = 0xffffffffu;

    uint32_t* Hs   = (uint32_t*)(smem + SM_H);
    float*    msg  = (float*)(smem + SM_H);      // same region, after MMA
    int*      sdst = (int*)(smem + SM_SDST);
    int*      ssrc = (int*)(smem + SM_SSRC);
    int*      segs = (int*)(smem + SM_SEGS);
    int*      segn = (int*)(smem + SM_SEGN);
    float*    bbs  = (float*)(smem + SM_BB);
    int*      swc  = (int*)(smem + SM_WC);
    int*      snseg= (int*)(smem + SM_NSEG);

    if (tid < 128) bbs[tid] = bb[tid];

    const int ntiles = (E + 127) >> 7;
    const int wM = wid & 3;      // edge-stripe  [wM*32, +32)
    const int wN = wid >> 2;     // out-half     [wN*64, +64)

    for (int t = blockIdx.x; t < ntiles; t += gridDim.x) {
        const int e0  = t << 7;
        const int cnt = min(128, E - e0);

        if (tid < 128) {
            sdst[tid] = (tid < cnt) ? sdst_g[e0 + tid] : -1;
            ssrc[tid] = (tid < cnt) ? ssrc_g[e0 + tid] : 0;
        }
        __syncthreads();

        // ---- segment heads (warps 0..3) ----
        int head = 0; unsigned bm = 0;
        if (tid < 128) {
            head = (tid < cnt) && (tid == 0 || sdst[tid] != sdst[tid - 1]);
            bm = __ballot_sync(FULL, head);
            if (lane == 0) swc[wid] = __popc(bm);
        }
        __syncthreads();
        if (tid == 0) {
            int s = 0;
            for (int w = 0; w < 4; w++) { swc[4 + w] = s; s += swc[w]; }
            snseg[0] = s;
            segs[s]  = cnt;
        }
        __syncthreads();
        if (head) {
            int sid = swc[4 + wid] + __popc(bm & ((1u << lane) - 1u));
            segs[sid] = tid;
            segn[sid] = sdst[tid];
        }

        // ---- gather: H[e][k] = tf32(relu(A[dst]+B[src])) ----
        {
            const int e    = tid >> 1;
            const int half = tid & 1;
            uint32_t* hr = Hs + e * HP + half * 64;
            if (e < cnt) {
                const size_t dr = (size_t)sdst[e] * 32 + half * 16;
                const size_t sr = (size_t)ssrc[e] * 32 + half * 16;
#pragma unroll
                for (int j = 0; j < 16; j++) {
                    float4 av = nodeA[dr + j];
                    float4 bv = nodeB[sr + j];
                    uint4 hv;
                    hv.x = f2tf32(fmaxf(av.x + bv.x, 0.f));
                    hv.y = f2tf32(fmaxf(av.y + bv.y, 0.f));
                    hv.z = f2tf32(fmaxf(av.z + bv.z, 0.f));
                    hv.w = f2tf32(fmaxf(av.w + bv.w, 0.f));
                    *(uint4*)(hr + j * 4) = hv;
                }
            } else {
#pragma unroll
                for (int j = 0; j < 16; j++)
                    *(uint4*)(hr + j * 4) = make_uint4(0u, 0u, 0u, 0u);
            }
        }
        __syncthreads();

        // ---- MMA: warp tile 32 edges x 64 outs; W from global (L1-hot) ----
        float acc[2][8][4];
#pragma unroll
        for (int mt = 0; mt < 2; mt++)
#pragma unroll
            for (int nt = 0; nt < 8; nt++)
#pragma unroll
                for (int r = 0; r < 4; r++) acc[mt][nt][r] = 0.f;

        const int g = lane >> 2, th = lane & 3;
        const uint4* wrow = wbp + (size_t)wN * 2048 + lane;
#pragma unroll 4
        for (int kk = 0; kk < 16; kk++) {
            uint32_t a[2][4];
#pragma unroll
            for (int mt = 0; mt < 2; mt++) {
                const uint32_t* base = Hs + (wM * 32 + mt * 16 + g) * HP + kk * 8 + th;
                a[mt][0] = base[0];
                a[mt][1] = base[8 * HP];
                a[mt][2] = base[4];
                a[mt][3] = base[8 * HP + 4];
            }
#pragma unroll
            for (int p = 0; p < 4; p++) {
                uint4 bp = wrow[(p * 16 + kk) * 32];
#pragma unroll
                for (int mt = 0; mt < 2; mt++) {
                    mma_tf32(acc[mt][2 * p],     a[mt], bp.x, bp.y);
                    mma_tf32(acc[mt][2 * p + 1], a[mt], bp.z, bp.w);
                }
            }
        }
        __syncthreads();   // all warps done reading H

        // ---- store D -> msg[e][c] ----
#pragma unroll
        for (int mt = 0; mt < 2; mt++) {
            const int row = wM * 32 + mt * 16 + g;
#pragma unroll
            for (int nt = 0; nt < 8; nt++) {
                const int col = wN * 64 + nt * 8 + 2 * th;
                *(float2*)(msg + row * HP + col) =
                    make_float2(acc[mt][nt][0], acc[mt][nt][1]);
                *(float2*)(msg + (row + 8) * HP + col) =
                    make_float2(acc[mt][nt][2], acc[mt][nt][3]);
            }
        }
        __syncthreads();

        // ---- segmented max + writeback ----
        {
            const int nseg = snseg[0];
            for (int i = tid; i < nseg * 128; i += 256) {
                const int c = i & 127;
                const int s = i >> 7;
                const int st = segs[s], en = segs[s + 1];
                float m = -3.4e38f;
                for (int e = st; e < en; e++)
                    m = fmaxf(m, msg[e * HP + c]);
                m += bbs[c];
                float* o = out + (size_t)segn[s] * OC + c;
                if (st == 0 || en == cnt) {
                    atomicMax((int*)o, __float_as_int(m));  // 0-init => relu free
                } else {
                    *o = fmaxf(m, 0.f);                     // sole writer
                }
            }
        }
        __syncthreads();
    }
}

// ---------------------------------------------------------------------------
// Final: concat(x2,x4,x6) [384] -> maxpool(24) -> 16 -> @ fw + fb
// ---------------------------------------------------------------------------
__global__ __launch_bounds__(256)
void final_kernel(const float* __restrict__ x2,
                  const float* __restrict__ x4,
                  const float* __restrict__ x6,
                  const float* __restrict__ fw,
                  const float* __restrict__ fb,
                  float* __restrict__ out,
                  int n_nodes)
{
    const unsigned FULL = 0xffffffffu;
    const int lane = threadIdx.x & 31;
    const int warp = blockIdx.x * (blockDim.x >> 5) + (threadIdx.x >> 5);
    const int nw   = gridDim.x * (blockDim.x >> 5);

    for (int n = warp; n < n_nodes; n += nw) {
        float m = -3.4e38f;
        int idx0 = lane * 12;
#pragma unroll
        for (int i = 0; i < 12; i++) {
            int idx = idx0 + i;
            float v;
            if (idx < 128)       v = x2[(size_t)n * OC + idx];
            else if (idx < 256)  v = x4[(size_t)n * OC + idx - 128];
            else                 v = x6[(size_t)n * OC + idx - 256];
            m = fmaxf(m, v);
        }
        float mm = fmaxf(m, __shfl_xor_sync(FULL, m, 1));
        float part = ((lane & 1) == 0) ? mm * fw[lane >> 1] : 0.f;
#pragma unroll
        for (int off = 16; off >= 1; off >>= 1)
            part += __shfl_xor_sync(FULL, part, off);
        if (lane == 0) out[n] = part + fb[0];
    }
}

// ---------------------------------------------------------------------------
extern "C" void kernel_launch(void* const* d_in, const int* in_sizes, int n_in,
                              void* d_out, int out_size)
{
    const float* x   = (const float*)d_in[0];
    const void*  ei  = d_in[1];
    const float* w1a = (const float*)d_in[2];  const float* b1a = (const float*)d_in[3];
    const float* w1b = (const float*)d_in[4];  const float* b1b = (const float*)d_in[5];
    const float* w2a = (const float*)d_in[6];  const float* b2a = (const float*)d_in[7];
    const float* w2b = (const float*)d_in[8];  const float* b2b = (const float*)d_in[9];
    const float* w3a = (const float*)d_in[10]; const float* b3a = (const float*)d_in[11];
    const float* w3b = (const float*)d_in[12]; const float* b3b = (const float*)d_in[13];
    const float* fw  = (const float*)d_in[14]; const float* fb  = (const float*)d_in[15];
    float* out = (float*)d_out;

    const int       N = in_sizes[0] / 24;
    const long long E = in_sizes[1] / 2;

    float *A, *B, *X2, *X4, *X6;
    int *deg, *off, *cur, *ssrc, *sdst;
    uint4 *wbp;
    cudaGetSymbolAddress((void**)&A,    g_A);
    cudaGetSymbolAddress((void**)&B,    g_B);
    cudaGetSymbolAddress((void**)&X2,   g_x2);
    cudaGetSymbolAddress((void**)&X4,   g_x4);
    cudaGetSymbolAddress((void**)&X6,   g_x6);
    cudaGetSymbolAddress((void**)&deg,  g_deg);
    cudaGetSymbolAddress((void**)&off,  g_off);
    cudaGetSymbolAddress((void**)&cur,  g_cur);
    cudaGetSymbolAddress((void**)&ssrc, g_ssrc);
    cudaGetSymbolAddress((void**)&sdst, g_sdst);
    cudaGetSymbolAddress((void**)&wbp,  g_wbp);

    cudaFuncSetAttribute(edge_mma_kernel,
                         cudaFuncAttributeMaxDynamicSharedMemorySize, SM_TOTAL);

    // ---- edge-index width + counting sort by dst ----
    detect_idx_kernel<<<1, 256>>>((const int*)ei);
    cudaMemsetAsync(deg, 0, (size_t)N * sizeof(int));
    cudaMemsetAsync(cur, 0, (size_t)N * sizeof(int));
    hist_kernel<<<512, 256>>>(ei, E, deg);
    scan_kernel<<<1, 1024>>>(deg, off, N);
    scatter_kernel<<<512, 256>>>(ei, E, off, cur, ssrc, sdst);

    // ---- weight prep (tf32 packed B fragments) ----
    prep_w_kernel<<<16, 256>>>(w1b, wbp);
    prep_w_kernel<<<16, 256>>>(w2b, wbp + 4096);
    prep_w_kernel<<<16, 256>>>(w3b, wbp + 8192);

    const int NPB = 8;
    const int node_grid = (N + NPB - 1) / NPB;
    const int edge_grid = 296;   // 2 CTAs/SM

    // Layer 1 (C = 24)
    node_kernel<24, 8><<<node_grid, 128>>>(x, w1a, b1a, A, B, X2, N);
    edge_mma_kernel<<<edge_grid, 256, SM_TOTAL>>>((const float4*)A, (const float4*)B,
        ssrc, sdst, wbp, b1b, X2, (int)E);
    // Layer 2 (C = 128)
    node_kernel<128, 8><<<node_grid, 128>>>(X2, w2a, b2a, A, B, X4, N);
    edge_mma_kernel<<<edge_grid, 256, SM_TOTAL>>>((const float4*)A, (const float4*)B,
        ssrc, sdst, wbp + 4096, b2b, X4, (int)E);
    // Layer 3 (C = 128)
    node_kernel<128, 8><<<node_grid, 128>>>(X4, w3a, b3a, A, B, X6, N);
    edge_mma_kernel<<<edge_grid, 256, SM_TOTAL>>>((const float4*)A, (const float4*)B,
        ssrc, sdst, wbp + 8192, b3b, X6, (int)E);

    // Pool + final linear
    final_kernel<<<(N + 7) / 8, 256>>>(X2, X4, X6, fw, fb, out, N);
}